// round 1
// baseline (speedup 1.0000x reference)
#include <cuda_runtime.h>
#include <cstdint>

#define N_NODES 50000
#define N_EDGES 1600000

// Scratch (device globals: allocation-free, graph-capturable)
__device__ float g_A[N_NODES * 64];      // xW scratch
__device__ float g_B[N_NODES * 64];      // H (aggregation) buffer
__device__ float g_deg[N_NODES];
__device__ float g_dinv[N_NODES];
__device__ float g_norm[N_EDGES];

// ---------------- small utility kernels ----------------

__global__ void k_fill(float* p, float v, int n) {
    int i = blockIdx.x * blockDim.x + threadIdx.x;
    if (i < n) p[i] = v;
}

__global__ void k_deg(const float* __restrict__ ew, const int* __restrict__ dst,
                      float* __restrict__ deg, int E) {
    int i = blockIdx.x * blockDim.x + threadIdx.x;
    if (i < E) atomicAdd(&deg[dst[i]], ew[i]);
}

__global__ void k_dinv(const float* __restrict__ deg, float* __restrict__ dinv, int n) {
    int i = blockIdx.x * blockDim.x + threadIdx.x;
    if (i < n) dinv[i] = rsqrtf(deg[i]);
}

__global__ void k_norm(const int* __restrict__ src, const int* __restrict__ dst,
                       const float* __restrict__ ew, const float* __restrict__ dinv,
                       float* __restrict__ norm, int E) {
    int i = blockIdx.x * blockDim.x + threadIdx.x;
    if (i < E) norm[i] = dinv[src[i]] * ew[i] * dinv[dst[i]];
}

// ---------------- fused GEMM + self-loop init ----------------
// One warp per row. Row of X held in registers (XPL floats/lane), broadcast via shfl.
// W staged in shared memory. Writes xW (for edge gather) and
// Hinit = dinv[row]^2 * xW + b (aggregation initializer). Optional ReLU on input.

template <int FIN, int FOUT, bool RELU_IN>
__global__ void gemm_self(const float* __restrict__ X, const float* __restrict__ W,
                          const float* __restrict__ bias, const float* __restrict__ dinv,
                          float* __restrict__ xW, float* __restrict__ Hinit, int n) {
    __shared__ float Ws[FIN * FOUT];
    __shared__ float bs[FOUT];
    for (int i = threadIdx.x; i < FIN * FOUT; i += blockDim.x) Ws[i] = W[i];
    for (int i = threadIdx.x; i < FOUT; i += blockDim.x) bs[i] = bias[i];
    __syncthreads();

    const int lane = threadIdx.x & 31;
    const int warpsPerBlock = blockDim.x >> 5;
    const int nwarps = warpsPerBlock * gridDim.x;
    int row0 = blockIdx.x * warpsPerBlock + (threadIdx.x >> 5);

    constexpr int XPL = FIN / 32;     // x floats per lane (4 or 2)
    const int c0 = lane * 2;          // two output columns per lane

    for (int row = row0; row < n; row += nwarps) {
        float xr[XPL];
        if (XPL == 4) {
            float4 t = reinterpret_cast<const float4*>(X)[row * (FIN / 4) + lane];
            xr[0] = t.x; xr[1] = t.y; xr[2] = t.z; xr[3] = t.w;
        } else {
            float2 t = reinterpret_cast<const float2*>(X)[row * (FIN / 2) + lane];
            xr[0] = t.x; xr[1] = t.y;
        }
        if (RELU_IN) {
#pragma unroll
            for (int j = 0; j < XPL; j++) xr[j] = fmaxf(xr[j], 0.0f);
        }

        float acc0 = 0.0f, acc1 = 0.0f;
#pragma unroll
        for (int k = 0; k < FIN; k++) {
            float xk = __shfl_sync(0xffffffffu, xr[k % XPL], k / XPL);
            if (c0 < FOUT) {
                float2 w2 = *reinterpret_cast<const float2*>(&Ws[k * FOUT + c0]);
                acc0 = fmaf(xk, w2.x, acc0);
                acc1 = fmaf(xk, w2.y, acc1);
            }
        }

        if (c0 < FOUT) {
            float di = dinv[row];
            float d2 = di * di;
            float2 a; a.x = acc0; a.y = acc1;
            *reinterpret_cast<float2*>(&xW[(size_t)row * FOUT + c0]) = a;
            float2 h;
            h.x = fmaf(d2, acc0, bs[c0]);
            h.y = fmaf(d2, acc1, bs[c0 + 1]);
            *reinterpret_cast<float2*>(&Hinit[(size_t)row * FOUT + c0]) = h;
        }
    }
}

// ---------------- edge aggregation ----------------
// 8 lanes per edge. Gather float4 from xW[src], scale by norm, vector-reduce
// (red.global.add.v4.f32, sm_90+) into H[dst]. L2-resident traffic.

template <int FOUT>
__global__ void edge_agg(const float* __restrict__ xW, const int* __restrict__ src,
                         const int* __restrict__ dst, const float* __restrict__ norm,
                         float* __restrict__ H, int E) {
    constexpr int NV = FOUT / 4;
    int t = blockIdx.x * blockDim.x + threadIdx.x;
    int g = t >> 3;
    int j = t & 7;
    if (g >= E) return;
    int s = src[g];
    int d = dst[g];
    float w = norm[g];
    const float4* xv = reinterpret_cast<const float4*>(xW + (size_t)s * FOUT);
    float* hb = H + (size_t)d * FOUT;
#pragma unroll
    for (int v = j; v < NV; v += 8) {
        float4 q = xv[v];
        q.x *= w; q.y *= w; q.z *= w; q.w *= w;
        asm volatile("red.global.add.v4.f32 [%0], {%1, %2, %3, %4};"
                     :: "l"(hb + 4 * v), "f"(q.x), "f"(q.y), "f"(q.z), "f"(q.w)
                     : "memory");
    }
}

// ---------------- host launcher ----------------

extern "C" void kernel_launch(void* const* d_in, const int* in_sizes, int n_in,
                              void* d_out, int out_size) {
    const float* x   = (const float*)d_in[0];
    const int*   ei  = (const int*)d_in[1];
    const float* ew  = (const float*)d_in[2];
    const float* W1  = (const float*)d_in[3];
    const float* b1  = (const float*)d_in[4];
    const float* W2  = (const float*)d_in[5];
    const float* b2  = (const float*)d_in[6];
    const float* W3  = (const float*)d_in[7];
    const float* b3  = (const float*)d_in[8];
    float* out = (float*)d_out;

    const int n = in_sizes[0] / 128;
    const int E = in_sizes[2];
    const int* src = ei;
    const int* dst = ei + E;

    float *A, *B, *deg, *dinv, *norm;
    cudaGetSymbolAddress((void**)&A, g_A);
    cudaGetSymbolAddress((void**)&B, g_B);
    cudaGetSymbolAddress((void**)&deg, g_deg);
    cudaGetSymbolAddress((void**)&dinv, g_dinv);
    cudaGetSymbolAddress((void**)&norm, g_norm);

    const int TB = 256;
    dim3 nblk((n + TB - 1) / TB);
    dim3 eblk((E + TB - 1) / TB);
    dim3 e8blk(((size_t)E * 8 + TB - 1) / TB);
    dim3 gblk(1024);

    // degree / dinv / per-edge norm (layer-invariant)
    k_fill<<<nblk, TB>>>(deg, 1.0f, n);
    k_deg<<<eblk, TB>>>(ew, dst, deg, E);
    k_dinv<<<nblk, TB>>>(deg, dinv, n);
    k_norm<<<eblk, TB>>>(src, dst, ew, dinv, norm, E);

    // Layer 1: 128 -> 64, ReLU deferred into layer-2 GEMM load
    gemm_self<128, 64, false><<<gblk, TB>>>(x, W1, b1, dinv, A, B, n);
    edge_agg<64><<<e8blk, TB>>>(A, src, dst, norm, B, E);

    // Layer 2: 64 -> 64 (reads relu(B) per-row, writes Hinit back into B in place)
    gemm_self<64, 64, true><<<gblk, TB>>>(B, W2, b2, dinv, A, B, n);
    edge_agg<64><<<e8blk, TB>>>(A, src, dst, norm, B, E);

    // Layer 3: 64 -> 40, output straight to d_out (no ReLU)
    gemm_self<64, 40, true><<<gblk, TB>>>(B, W3, b3, dinv, A, out, n);
    edge_agg<40><<<e8blk, TB>>>(A, src, dst, norm, out, E);
}

// round 2
// speedup vs baseline: 1.2003x; 1.2003x over previous
#include <cuda_runtime.h>
#include <cstdint>

#define N_NODES 50000
#define N_EDGES 1600000

// Scratch (device globals: allocation-free, graph-capturable)
__device__ float g_A[N_NODES * 64];       // xW scratch
__device__ float g_B[N_NODES * 64];       // H buffer
__device__ float g_deg[N_NODES];
__device__ float g_dinv[N_NODES];
__device__ int   g_cnt[N_NODES];
__device__ int   g_rowptr[N_NODES + 1];
__device__ int   g_wpos[N_NODES];
__device__ int   g_bsum[256];
__device__ int   g_src_sorted[N_EDGES];
__device__ float g_norm_sorted[N_EDGES];

// ---------------- prelude: degree + counting sort by dst ----------------

__global__ void k_init(float* deg, int* cnt, int n) {
    int i = blockIdx.x * blockDim.x + threadIdx.x;
    if (i < n) { deg[i] = 1.0f; cnt[i] = 0; }   // 1.0 = self-loop weight
}

__global__ void k_count(const float* __restrict__ ew, const int* __restrict__ dst,
                        float* __restrict__ deg, int* __restrict__ cnt, int E) {
    int i = blockIdx.x * blockDim.x + threadIdx.x;
    if (i < E) {
        int d = dst[i];
        atomicAdd(&deg[d], ew[i]);
        atomicAdd(&cnt[d], 1);
    }
}

__global__ void k_dinv(const float* __restrict__ deg, float* __restrict__ dinv, int n) {
    int i = blockIdx.x * blockDim.x + threadIdx.x;
    if (i < n) dinv[i] = rsqrtf(deg[i]);
}

// 3-kernel exclusive scan over cnt[0..n) -> rowptr / wpos
__global__ void k_scan1(const int* __restrict__ cnt, int* __restrict__ rowptr,
                        int* __restrict__ bsum, int n) {
    __shared__ int sh[256];
    int i = blockIdx.x * 256 + threadIdx.x;
    int v = (i < n) ? cnt[i] : 0;
    sh[threadIdx.x] = v;
    __syncthreads();
#pragma unroll
    for (int off = 1; off < 256; off <<= 1) {
        int t = (threadIdx.x >= off) ? sh[threadIdx.x - off] : 0;
        __syncthreads();
        sh[threadIdx.x] += t;
        __syncthreads();
    }
    if (i < n) rowptr[i] = sh[threadIdx.x] - v;          // exclusive within block
    if (threadIdx.x == 255) bsum[blockIdx.x] = sh[255];  // block total
}

__global__ void k_scan2(int* __restrict__ bsum, int nb) {
    __shared__ int sh[256];
    int v = (threadIdx.x < nb) ? bsum[threadIdx.x] : 0;
    sh[threadIdx.x] = v;
    __syncthreads();
#pragma unroll
    for (int off = 1; off < 256; off <<= 1) {
        int t = (threadIdx.x >= off) ? sh[threadIdx.x - off] : 0;
        __syncthreads();
        sh[threadIdx.x] += t;
        __syncthreads();
    }
    if (threadIdx.x < nb) bsum[threadIdx.x] = sh[threadIdx.x] - v;  // exclusive
}

__global__ void k_scan3(int* __restrict__ rowptr, int* __restrict__ wpos,
                        const int* __restrict__ bsum, int n, int E) {
    int i = blockIdx.x * 256 + threadIdx.x;
    if (i < n) {
        int r = rowptr[i] + bsum[blockIdx.x];
        rowptr[i] = r;
        wpos[i] = r;
    }
    if (i == 0) rowptr[n] = E;
}

// Scatter edges into dst-sorted order; fuse per-edge norm computation.
__global__ void k_scatter(const int* __restrict__ src, const int* __restrict__ dst,
                          const float* __restrict__ ew, const float* __restrict__ dinv,
                          int* __restrict__ wpos, int* __restrict__ src_sorted,
                          float* __restrict__ norm_sorted, int E) {
    int i = blockIdx.x * blockDim.x + threadIdx.x;
    if (i < E) {
        int s = src[i], d = dst[i];
        int p = atomicAdd(&wpos[d], 1);
        src_sorted[p] = s;
        norm_sorted[p] = dinv[s] * ew[i] * dinv[d];
    }
}

// ---------------- GEMM: xW only (self-loop handled in agg) ----------------
// One warp per row; row in registers, broadcast via shfl; W in shared.

template <int FIN, int FOUT, bool RELU_IN>
__global__ void gemm_xw(const float* __restrict__ X, const float* __restrict__ W,
                        float* __restrict__ xW, int n) {
    __shared__ float Ws[FIN * FOUT];
    for (int i = threadIdx.x; i < FIN * FOUT; i += blockDim.x) Ws[i] = W[i];
    __syncthreads();

    const int lane = threadIdx.x & 31;
    const int warpsPerBlock = blockDim.x >> 5;
    const int nwarps = warpsPerBlock * gridDim.x;
    int row0 = blockIdx.x * warpsPerBlock + (threadIdx.x >> 5);

    constexpr int XPL = FIN / 32;
    const int c0 = lane * 2;

    for (int row = row0; row < n; row += nwarps) {
        float xr[XPL];
        if (XPL == 4) {
            float4 t = reinterpret_cast<const float4*>(X)[row * (FIN / 4) + lane];
            xr[0] = t.x; xr[1] = t.y; xr[2] = t.z; xr[3] = t.w;
        } else {
            float2 t = reinterpret_cast<const float2*>(X)[row * (FIN / 2) + lane];
            xr[0] = t.x; xr[1] = t.y;
        }
        if (RELU_IN) {
#pragma unroll
            for (int j = 0; j < XPL; j++) xr[j] = fmaxf(xr[j], 0.0f);
        }

        float acc0 = 0.0f, acc1 = 0.0f;
#pragma unroll
        for (int k = 0; k < FIN; k++) {
            float xk = __shfl_sync(0xffffffffu, xr[k % XPL], k / XPL);
            if (c0 < FOUT) {
                float2 w2 = *reinterpret_cast<const float2*>(&Ws[k * FOUT + c0]);
                acc0 = fmaf(xk, w2.x, acc0);
                acc1 = fmaf(xk, w2.y, acc1);
            }
        }
        if (c0 < FOUT) {
            float2 a; a.x = acc0; a.y = acc1;
            *reinterpret_cast<float2*>(&xW[(size_t)row * FOUT + c0]) = a;
        }
    }
}

// ---------------- CSR aggregation: one warp per dst node, atomic-free ----------
// acc = bias + dinv[node]^2 * xW[node] + sum_e norm[e] * xW[src[e]]

template <int FOUT>
__global__ void agg_csr(const float* __restrict__ xW, const int* __restrict__ rowptr,
                        const int* __restrict__ srcs, const float* __restrict__ nrm,
                        const float* __restrict__ bias, const float* __restrict__ dinv,
                        float* __restrict__ H, int n) {
    int node = (blockIdx.x * blockDim.x + threadIdx.x) >> 5;
    if (node >= n) return;
    int lane = threadIdx.x & 31;
    int c0 = lane * 2;
    const bool act = (c0 < FOUT);

    float2 acc = make_float2(0.0f, 0.0f);
    if (act) {
        float di = dinv[node];
        float ws = di * di;
        float2 v = *reinterpret_cast<const float2*>(xW + (size_t)node * FOUT + c0);
        acc.x = fmaf(ws, v.x, __ldg(&bias[c0]));
        acc.y = fmaf(ws, v.y, __ldg(&bias[c0 + 1]));
    }

    int e = rowptr[node];
    const int end = rowptr[node + 1];

    for (; e + 3 < end; e += 4) {
        int s0 = srcs[e], s1 = srcs[e + 1], s2 = srcs[e + 2], s3 = srcs[e + 3];
        float w0 = nrm[e], w1 = nrm[e + 1], w2 = nrm[e + 2], w3 = nrm[e + 3];
        if (act) {
            float2 v0 = *reinterpret_cast<const float2*>(xW + (size_t)s0 * FOUT + c0);
            float2 v1 = *reinterpret_cast<const float2*>(xW + (size_t)s1 * FOUT + c0);
            float2 v2 = *reinterpret_cast<const float2*>(xW + (size_t)s2 * FOUT + c0);
            float2 v3 = *reinterpret_cast<const float2*>(xW + (size_t)s3 * FOUT + c0);
            acc.x = fmaf(w0, v0.x, acc.x); acc.y = fmaf(w0, v0.y, acc.y);
            acc.x = fmaf(w1, v1.x, acc.x); acc.y = fmaf(w1, v1.y, acc.y);
            acc.x = fmaf(w2, v2.x, acc.x); acc.y = fmaf(w2, v2.y, acc.y);
            acc.x = fmaf(w3, v3.x, acc.x); acc.y = fmaf(w3, v3.y, acc.y);
        }
    }
    for (; e < end; e++) {
        int s = srcs[e];
        float w = nrm[e];
        if (act) {
            float2 v = *reinterpret_cast<const float2*>(xW + (size_t)s * FOUT + c0);
            acc.x = fmaf(w, v.x, acc.x);
            acc.y = fmaf(w, v.y, acc.y);
        }
    }

    if (act)
        *reinterpret_cast<float2*>(H + (size_t)node * FOUT + c0) = acc;
}

// ---------------- host launcher ----------------

extern "C" void kernel_launch(void* const* d_in, const int* in_sizes, int n_in,
                              void* d_out, int out_size) {
    const float* x  = (const float*)d_in[0];
    const int*   ei = (const int*)d_in[1];
    const float* ew = (const float*)d_in[2];
    const float* W1 = (const float*)d_in[3];
    const float* b1 = (const float*)d_in[4];
    const float* W2 = (const float*)d_in[5];
    const float* b2 = (const float*)d_in[6];
    const float* W3 = (const float*)d_in[7];
    const float* b3 = (const float*)d_in[8];
    float* out = (float*)d_out;

    const int n = in_sizes[0] / 128;
    const int E = in_sizes[2];
    const int* src = ei;
    const int* dst = ei + E;

    float *A, *B, *deg, *dinv, *nrm;
    int *cnt, *rowptr, *wpos, *bsum, *ssrc;
    cudaGetSymbolAddress((void**)&A, g_A);
    cudaGetSymbolAddress((void**)&B, g_B);
    cudaGetSymbolAddress((void**)&deg, g_deg);
    cudaGetSymbolAddress((void**)&dinv, g_dinv);
    cudaGetSymbolAddress((void**)&cnt, g_cnt);
    cudaGetSymbolAddress((void**)&rowptr, g_rowptr);
    cudaGetSymbolAddress((void**)&wpos, g_wpos);
    cudaGetSymbolAddress((void**)&bsum, g_bsum);
    cudaGetSymbolAddress((void**)&ssrc, g_src_sorted);
    cudaGetSymbolAddress((void**)&nrm, g_norm_sorted);

    const int TB = 256;
    dim3 nblk((n + TB - 1) / TB);
    dim3 eblk((E + TB - 1) / TB);
    const int nb256 = (n + 255) / 256;      // scan geometry (196 blocks <= 256)
    dim3 aggblk((n * 32 + TB - 1) / TB);    // one warp per node
    dim3 gblk(6250);                        // one warp per row (50k warps)

    // ---- CSR build (layer-invariant) ----
    k_init<<<nblk, TB>>>(deg, cnt, n);
    k_count<<<eblk, TB>>>(ew, dst, deg, cnt, E);
    k_dinv<<<nblk, TB>>>(deg, dinv, n);
    k_scan1<<<nb256, 256>>>(cnt, rowptr, bsum, n);
    k_scan2<<<1, 256>>>(bsum, nb256);
    k_scan3<<<nb256, 256>>>(rowptr, wpos, bsum, n, E);
    k_scatter<<<eblk, TB>>>(src, dst, ew, dinv, wpos, ssrc, nrm, E);

    // ---- Layer 1: 128 -> 64 ----
    gemm_xw<128, 64, false><<<gblk, TB>>>(x, W1, A, n);
    agg_csr<64><<<aggblk, TB>>>(A, rowptr, ssrc, nrm, b1, dinv, B, n);

    // ---- Layer 2: 64 -> 64 (ReLU fused into GEMM load) ----
    gemm_xw<64, 64, true><<<gblk, TB>>>(B, W2, A, n);
    agg_csr<64><<<aggblk, TB>>>(A, rowptr, ssrc, nrm, b2, dinv, B, n);

    // ---- Layer 3: 64 -> 40 ----
    gemm_xw<64, 40, true><<<gblk, TB>>>(B, W3, A, n);
    agg_csr<40><<<aggblk, TB>>>(A, rowptr, ssrc, nrm, b3, dinv, out, n);
}

// round 4
// speedup vs baseline: 1.3533x; 1.1274x over previous
#include <cuda_runtime.h>
#include <cstdint>

#define N_NODES 50000
#define N_EDGES 1600000

// Scratch (device globals: allocation-free, graph-capturable)
__device__ float g_A[N_NODES * 64];       // xW scratch
__device__ float g_B[N_NODES * 64];       // H buffer
__device__ float g_deg[N_NODES];
__device__ float g_dinv[N_NODES];
__device__ int   g_cnt[N_NODES];
__device__ int   g_rowptr[N_NODES + 1];
__device__ int   g_wpos[N_NODES];
__device__ int   g_bsum[256];
__device__ int2  g_meta[N_EDGES];         // (src, norm-as-int) sorted by dst

// ---------------- prelude: degree + counting sort by dst ----------------

__global__ void k_init(float* deg, int* cnt, int n) {
    int i = blockIdx.x * blockDim.x + threadIdx.x;
    if (i < n) { deg[i] = 1.0f; cnt[i] = 0; }   // 1.0 = self-loop weight
}

__global__ void k_count(const float* __restrict__ ew, const int* __restrict__ dst,
                        float* __restrict__ deg, int* __restrict__ cnt, int E) {
    int i = blockIdx.x * blockDim.x + threadIdx.x;
    if (i < E) {
        int d = dst[i];
        atomicAdd(&deg[d], ew[i]);
        atomicAdd(&cnt[d], 1);
    }
}

// scan pass 1 over cnt -> per-block exclusive prefix; also computes dinv (deg ready)
__global__ void k_scan1(const int* __restrict__ cnt, int* __restrict__ rowptr,
                        int* __restrict__ bsum, const float* __restrict__ deg,
                        float* __restrict__ dinv, int n) {
    __shared__ int sh[256];
    int i = blockIdx.x * 256 + threadIdx.x;
    int v = (i < n) ? cnt[i] : 0;
    if (i < n) dinv[i] = rsqrtf(deg[i]);
    sh[threadIdx.x] = v;
    __syncthreads();
#pragma unroll
    for (int off = 1; off < 256; off <<= 1) {
        int t = (threadIdx.x >= off) ? sh[threadIdx.x - off] : 0;
        __syncthreads();
        sh[threadIdx.x] += t;
        __syncthreads();
    }
    if (i < n) rowptr[i] = sh[threadIdx.x] - v;
    if (threadIdx.x == 255) bsum[blockIdx.x] = sh[255];
}

__global__ void k_scan2(int* __restrict__ bsum, int nb) {
    __shared__ int sh[256];
    int v = (threadIdx.x < nb) ? bsum[threadIdx.x] : 0;
    sh[threadIdx.x] = v;
    __syncthreads();
#pragma unroll
    for (int off = 1; off < 256; off <<= 1) {
        int t = (threadIdx.x >= off) ? sh[threadIdx.x - off] : 0;
        __syncthreads();
        sh[threadIdx.x] += t;
        __syncthreads();
    }
    if (threadIdx.x < nb) bsum[threadIdx.x] = sh[threadIdx.x] - v;
}

__global__ void k_scan3(int* __restrict__ rowptr, int* __restrict__ wpos,
                        const int* __restrict__ bsum, int n, int E) {
    int i = blockIdx.x * 256 + threadIdx.x;
    if (i < n) {
        int r = rowptr[i] + bsum[blockIdx.x];
        rowptr[i] = r;
        wpos[i] = r;
    }
    if (i == 0) rowptr[n] = E;
}

// Scatter edges into dst-sorted order; fused norm; single int2 store per edge.
__global__ void k_scatter(const int* __restrict__ src, const int* __restrict__ dst,
                          const float* __restrict__ ew, const float* __restrict__ dinv,
                          int* __restrict__ wpos, int2* __restrict__ meta, int E) {
    int i = blockIdx.x * blockDim.x + threadIdx.x;
    if (i < E) {
        int s = src[i], d = dst[i];
        int p = atomicAdd(&wpos[d], 1);
        float w = dinv[s] * ew[i] * dinv[d];
        meta[p] = make_int2(s, __float_as_int(w));
    }
}

// ---------------- GEMM: xW, 4 rows/warp, packed f32x2 FMA ----------------
// Each warp: 4 rows; lane owns 2 output cols (one packed f32x2 acc per row).
// W staged in shared; one LDS.64 of W feeds 4 rows (LDS bytes /4 vs 1-row/warp).

template <int FIN, int FOUT, bool RELU_IN>
__global__ void gemm_xw(const float* __restrict__ X, const float* __restrict__ W,
                        float* __restrict__ xW, int n) {
    __shared__ float Ws[FIN * FOUT];
    for (int i = threadIdx.x; i < FIN * FOUT; i += blockDim.x) Ws[i] = W[i];
    __syncthreads();

    const int lane = threadIdx.x & 31;
    const int wq = blockIdx.x * (blockDim.x >> 5) + (threadIdx.x >> 5);  // warp id
    const int row0 = wq * 4;
    if (row0 >= n) return;

    constexpr int XPL = FIN / 32;
    const int c0 = lane * 2;
    const bool act = (c0 < FOUT);

    float xr[4][XPL];
#pragma unroll
    for (int r = 0; r < 4; r++) {
        int row = row0 + r;
        if (row < n) {
            if (XPL == 4) {
                float4 t = reinterpret_cast<const float4*>(X)[row * (FIN / 4) + lane];
                xr[r][0] = t.x; xr[r][1] = t.y; xr[r][2] = t.z; xr[r][3] = t.w;
            } else {
                float2 t = reinterpret_cast<const float2*>(X)[row * (FIN / 2) + lane];
                xr[r][0] = t.x; xr[r][1] = t.y;
            }
            if (RELU_IN) {
#pragma unroll
                for (int j = 0; j < XPL; j++) xr[r][j] = fmaxf(xr[r][j], 0.0f);
            }
        } else {
#pragma unroll
            for (int j = 0; j < XPL; j++) xr[r][j] = 0.0f;
        }
    }

    unsigned long long acc[4] = {0ull, 0ull, 0ull, 0ull};   // packed {f32,f32} pairs

#pragma unroll
    for (int k = 0; k < FIN; k++) {
        unsigned long long ww = 0ull;
        if (act)
            ww = *reinterpret_cast<const unsigned long long*>(&Ws[k * FOUT + c0]);
#pragma unroll
        for (int r = 0; r < 4; r++) {
            float xk = __shfl_sync(0xffffffffu, xr[r][k % XPL], k / XPL);
            if (act) {
                unsigned long long xx;
                asm("mov.b64 %0, {%1, %1};" : "=l"(xx) : "f"(xk));
                asm("fma.rn.f32x2 %0, %1, %2, %3;"
                    : "=l"(acc[r]) : "l"(xx), "l"(ww), "l"(acc[r]));
            }
        }
    }

    if (act) {
#pragma unroll
        for (int r = 0; r < 4; r++) {
            int row = row0 + r;
            if (row < n) {
                float2 a;
                asm("mov.b64 {%0, %1}, %2;" : "=f"(a.x), "=f"(a.y) : "l"(acc[r]));
                *reinterpret_cast<float2*>(&xW[(size_t)row * FOUT + c0]) = a;
            }
        }
    }
}

// ---------------- CSR aggregation: half-warp per node, float4, atomic-free ----
// acc = bias + dinv[node]^2 * xW[node] + sum_e norm[e] * xW[src[e]]
// Metadata: 16 (src,norm) pairs loaded by one LDG.64/lane, broadcast via shfl-16.

template <int FOUT>
__global__ void agg_csr(const float* __restrict__ xW, const int* __restrict__ rowptr,
                        const int2* __restrict__ meta, const float* __restrict__ bias,
                        const float* __restrict__ dinv, float* __restrict__ H, int n) {
    const int warp = (blockIdx.x * blockDim.x + threadIdx.x) >> 5;
    const int lane = threadIdx.x & 31;
    const int half = lane >> 4;
    const int sub = lane & 15;
    const int node = warp * 2 + half;
    const unsigned hmask = half ? 0xFFFF0000u : 0x0000FFFFu;
    const bool valid = node < n;

    const int c0 = sub * 4;
    const bool act = valid && (c0 < FOUT);

    float4 acc = make_float4(0.f, 0.f, 0.f, 0.f);
    if (act) {
        float di = dinv[node];
        float ws = di * di;
        float4 v = *reinterpret_cast<const float4*>(xW + (size_t)node * FOUT + c0);
        float4 b = *reinterpret_cast<const float4*>(bias + c0);
        acc.x = fmaf(ws, v.x, b.x);
        acc.y = fmaf(ws, v.y, b.y);
        acc.z = fmaf(ws, v.z, b.z);
        acc.w = fmaf(ws, v.w, b.w);
    }

    int e = valid ? rowptr[node] : 0;
    const int end = valid ? rowptr[node + 1] : 0;

    while (e < end) {
        int cnt = min(end - e, 16);
        int2 pr = make_int2(0, 0);
        if (sub < cnt) pr = meta[e + sub];

        if (cnt == 16) {
#pragma unroll
            for (int j = 0; j < 16; j++) {
                int s = __shfl_sync(hmask, pr.x, j, 16);
                float w = __int_as_float(__shfl_sync(hmask, pr.y, j, 16));
                if (act) {
                    float4 v = *reinterpret_cast<const float4*>(xW + (size_t)s * FOUT + c0);
                    acc.x = fmaf(w, v.x, acc.x);
                    acc.y = fmaf(w, v.y, acc.y);
                    acc.z = fmaf(w, v.z, acc.z);
                    acc.w = fmaf(w, v.w, acc.w);
                }
            }
        } else {
            for (int j = 0; j < cnt; j++) {
                int s = __shfl_sync(hmask, pr.x, j, 16);
                float w = __int_as_float(__shfl_sync(hmask, pr.y, j, 16));
                if (act) {
                    float4 v = *reinterpret_cast<const float4*>(xW + (size_t)s * FOUT + c0);
                    acc.x = fmaf(w, v.x, acc.x);
                    acc.y = fmaf(w, v.y, acc.y);
                    acc.z = fmaf(w, v.z, acc.z);
                    acc.w = fmaf(w, v.w, acc.w);
                }
            }
        }
        e += cnt;
    }

    if (act)
        *reinterpret_cast<float4*>(H + (size_t)node * FOUT + c0) = acc;
}

// ---------------- host launcher ----------------

extern "C" void kernel_launch(void* const* d_in, const int* in_sizes, int n_in,
                              void* d_out, int out_size) {
    const float* x  = (const float*)d_in[0];
    const int*   ei = (const int*)d_in[1];
    const float* ew = (const float*)d_in[2];
    const float* W1 = (const float*)d_in[3];
    const float* b1 = (const float*)d_in[4];
    const float* W2 = (const float*)d_in[5];
    const float* b2 = (const float*)d_in[6];
    const float* W3 = (const float*)d_in[7];
    const float* b3 = (const float*)d_in[8];
    float* out = (float*)d_out;

    const int n = in_sizes[0] / 128;
    const int E = in_sizes[2];
    const int* src = ei;
    const int* dst = ei + E;

    float *A, *B, *deg, *dinv;
    int *cnt, *rowptr, *wpos, *bsum;
    int2 *meta;
    cudaGetSymbolAddress((void**)&A, g_A);
    cudaGetSymbolAddress((void**)&B, g_B);
    cudaGetSymbolAddress((void**)&deg, g_deg);
    cudaGetSymbolAddress((void**)&dinv, g_dinv);
    cudaGetSymbolAddress((void**)&cnt, g_cnt);
    cudaGetSymbolAddress((void**)&rowptr, g_rowptr);
    cudaGetSymbolAddress((void**)&wpos, g_wpos);
    cudaGetSymbolAddress((void**)&bsum, g_bsum);
    cudaGetSymbolAddress((void**)&meta, g_meta);

    const int TB = 256;
    dim3 nblk((n + TB - 1) / TB);
    dim3 eblk((E + TB - 1) / TB);
    const int nb256 = (n + 255) / 256;
    // agg: 2 nodes per warp, 8 warps per block -> 16 nodes per block
    dim3 aggblk((n + 15) / 16);
    // gemm: 4 rows per warp, 8 warps per block -> 32 rows per block
    dim3 gblk((n + 31) / 32);           // FIX: was (n+255)/256, covered only 6272 rows

    // ---- CSR build (layer-invariant) ----
    k_init<<<nblk, TB>>>(deg, cnt, n);
    k_count<<<eblk, TB>>>(ew, dst, deg, cnt, E);
    k_scan1<<<nb256, 256>>>(cnt, rowptr, bsum, deg, dinv, n);
    k_scan2<<<1, 256>>>(bsum, nb256);
    k_scan3<<<nb256, 256>>>(rowptr, wpos, bsum, n, E);
    k_scatter<<<eblk, TB>>>(src, dst, ew, dinv, wpos, meta, E);

    // ---- Layer 1: 128 -> 64 ----
    gemm_xw<128, 64, false><<<gblk, TB>>>(x, W1, A, n);
    agg_csr<64><<<aggblk, TB>>>(A, rowptr, meta, b1, dinv, B, n);

    // ---- Layer 2: 64 -> 64 (ReLU fused into GEMM load) ----
    gemm_xw<64, 64, true><<<gblk, TB>>>(B, W2, A, n);
    agg_csr<64><<<aggblk, TB>>>(A, rowptr, meta, b2, dinv, B, n);

    // ---- Layer 3: 64 -> 40 ----
    gemm_xw<64, 40, true><<<gblk, TB>>>(B, W3, A, n);
    agg_csr<40><<<aggblk, TB>>>(A, rowptr, meta, b3, dinv, out, n);
}

// round 5
// speedup vs baseline: 1.4199x; 1.0492x over previous
#include <cuda_runtime.h>
#include <cstdint>

#define N_NODES 50000
#define N_EDGES 1600000
#define SCAN_NB ((N_NODES + 255) / 256)   // 196

// Scratch (device globals: allocation-free, graph-capturable)
__device__ float g_A[N_NODES * 64];                 // xW scratch
__device__ float g_B[N_NODES * 64];                 // H buffer
__device__ float g_dinv[N_NODES];
__device__ unsigned long long g_pack[N_NODES];      // (cnt<<32) | fixpoint(sum ew)
__device__ unsigned long long g_state[SCAN_NB];     // lookback scan state
__device__ int   g_rowptr[N_NODES + 1];
__device__ int   g_wpos[N_NODES];
__device__ int2  g_meta[N_EDGES];                   // (src, norm-as-int) sorted by dst

// ---------------- prelude ----------------

__global__ void k_init(unsigned long long* pack, unsigned long long* state, int n) {
    int i = blockIdx.x * blockDim.x + threadIdx.x;
    if (i < n) pack[i] = 0ull;
    if (i < SCAN_NB) state[i] = 0ull;
}

// One RED.64 per edge: count in hi word, ew in 2^-20 fixed point in lo word.
// lo sum < deg_max * 2^20 << 2^32, never carries into hi.
__global__ void k_count(const float* __restrict__ ew, const int* __restrict__ dst,
                        unsigned long long* __restrict__ pack, int E) {
    int i = blockIdx.x * blockDim.x + threadIdx.x;
    if (i < E) {
        unsigned q = __float2uint_rn(ew[i] * 1048576.0f);
        atomicAdd(&pack[dst[i]], (1ull << 32) | (unsigned long long)q);
    }
}

// Single-kernel exclusive scan (decoupled lookback) + dinv computation.
__global__ void k_scan(const unsigned long long* __restrict__ pack,
                       int* __restrict__ rowptr, int* __restrict__ wpos,
                       float* __restrict__ dinv, unsigned long long* __restrict__ state,
                       int n, int E) {
    __shared__ int sh[256];
    __shared__ int s_prefix;
    const int b = blockIdx.x;
    const int i = b * 256 + threadIdx.x;

    unsigned long long p = (i < n) ? pack[i] : 0ull;
    int v = (int)(p >> 32);
    if (i < n) {
        float deg = 1.0f + (float)(unsigned)(p & 0xFFFFFFFFull) * (1.0f / 1048576.0f);
        dinv[i] = rsqrtf(deg);
    }

    sh[threadIdx.x] = v;
    __syncthreads();
#pragma unroll
    for (int off = 1; off < 256; off <<= 1) {
        int t = (threadIdx.x >= off) ? sh[threadIdx.x - off] : 0;
        __syncthreads();
        sh[threadIdx.x] += t;
        __syncthreads();
    }
    const int incl = sh[threadIdx.x];
    const int total = sh[255];

    if (threadIdx.x < 32) {
        const int lane = threadIdx.x;
        if (lane == 0) {
            unsigned long long st0 =
                ((unsigned long long)total << 2) | (b == 0 ? 2ull : 1ull);
            atomicExch(&state[b], st0);
        }
        int prefix = 0;
        if (b > 0) {
            int j = b - 1;
            while (true) {
                int idx = j - lane;
                unsigned long long s =
                    (idx >= 0) ? atomicAdd(&state[idx], 0ull) : 2ull;  // fake inclusive(0)
                unsigned st = (unsigned)(s & 3ull);
                unsigned ready = __ballot_sync(0xffffffffu, st != 0u);
                if (ready != 0xffffffffu) continue;  // some predecessor pending
                unsigned inclmask = __ballot_sync(0xffffffffu, st == 2u);
                if (inclmask) {
                    int l2 = __ffs(inclmask) - 1;    // nearest inclusive (largest idx)
                    int contrib = (lane <= l2) ? (int)(s >> 2) : 0;
#pragma unroll
                    for (int o = 16; o; o >>= 1)
                        contrib += __shfl_down_sync(0xffffffffu, contrib, o);
                    prefix += __shfl_sync(0xffffffffu, contrib, 0);
                    break;
                } else {
                    int contrib = (idx >= 0) ? (int)(s >> 2) : 0;
#pragma unroll
                    for (int o = 16; o; o >>= 1)
                        contrib += __shfl_down_sync(0xffffffffu, contrib, o);
                    prefix += __shfl_sync(0xffffffffu, contrib, 0);
                    j -= 32;
                }
            }
            if (lane == 0)
                atomicExch(&state[b],
                           ((unsigned long long)(prefix + total) << 2) | 2ull);
        }
        if (lane == 0) s_prefix = prefix;
    }
    __syncthreads();

    if (i < n) {
        int r = s_prefix + incl - v;
        rowptr[i] = r;
        wpos[i] = r;
        if (i == n - 1) rowptr[n] = E;
    }
}

// Scatter edges into dst-sorted order; fused norm; single int2 store per edge.
__global__ void k_scatter(const int* __restrict__ src, const int* __restrict__ dst,
                          const float* __restrict__ ew, const float* __restrict__ dinv,
                          int* __restrict__ wpos, int2* __restrict__ meta, int E) {
    int i = blockIdx.x * blockDim.x + threadIdx.x;
    if (i < E) {
        int s = src[i], d = dst[i];
        int p = atomicAdd(&wpos[d], 1);
        float w = dinv[s] * ew[i] * dinv[d];
        meta[p] = make_int2(s, __float_as_int(w));
    }
}

// ---------------- GEMM: xW, 4 rows/warp, packed f32x2 FMA ----------------

template <int FIN, int FOUT, bool RELU_IN>
__global__ void gemm_xw(const float* __restrict__ X, const float* __restrict__ W,
                        float* __restrict__ xW, int n) {
    __shared__ float Ws[FIN * FOUT];
    for (int i = threadIdx.x; i < FIN * FOUT; i += blockDim.x) Ws[i] = W[i];
    __syncthreads();

    const int lane = threadIdx.x & 31;
    const int wq = blockIdx.x * (blockDim.x >> 5) + (threadIdx.x >> 5);
    const int row0 = wq * 4;
    if (row0 >= n) return;

    constexpr int XPL = FIN / 32;
    const int c0 = lane * 2;
    const bool act = (c0 < FOUT);

    float xr[4][XPL];
#pragma unroll
    for (int r = 0; r < 4; r++) {
        int row = row0 + r;
        if (row < n) {
            if (XPL == 4) {
                float4 t = reinterpret_cast<const float4*>(X)[row * (FIN / 4) + lane];
                xr[r][0] = t.x; xr[r][1] = t.y; xr[r][2] = t.z; xr[r][3] = t.w;
            } else {
                float2 t = reinterpret_cast<const float2*>(X)[row * (FIN / 2) + lane];
                xr[r][0] = t.x; xr[r][1] = t.y;
            }
            if (RELU_IN) {
#pragma unroll
                for (int j = 0; j < XPL; j++) xr[r][j] = fmaxf(xr[r][j], 0.0f);
            }
        } else {
#pragma unroll
            for (int j = 0; j < XPL; j++) xr[r][j] = 0.0f;
        }
    }

    unsigned long long acc[4] = {0ull, 0ull, 0ull, 0ull};

#pragma unroll
    for (int k = 0; k < FIN; k++) {
        unsigned long long ww = 0ull;
        if (act)
            ww = *reinterpret_cast<const unsigned long long*>(&Ws[k * FOUT + c0]);
#pragma unroll
        for (int r = 0; r < 4; r++) {
            float xk = __shfl_sync(0xffffffffu, xr[r][k % XPL], k / XPL);
            if (act) {
                unsigned long long xx;
                asm("mov.b64 %0, {%1, %1};" : "=l"(xx) : "f"(xk));
                asm("fma.rn.f32x2 %0, %1, %2, %3;"
                    : "=l"(acc[r]) : "l"(xx), "l"(ww), "l"(acc[r]));
            }
        }
    }

    if (act) {
#pragma unroll
        for (int r = 0; r < 4; r++) {
            int row = row0 + r;
            if (row < n) {
                float2 a;
                asm("mov.b64 {%0, %1}, %2;" : "=f"(a.x), "=f"(a.y) : "l"(acc[r]));
                *reinterpret_cast<float2*>(&xW[(size_t)row * FOUT + c0]) = a;
            }
        }
    }
}

// ---------------- CSR aggregation: half-warp per node, float4, prefetched ----

template <int FOUT>
__global__ void agg_csr(const float* __restrict__ xW, const int* __restrict__ rowptr,
                        const int2* __restrict__ meta, const float* __restrict__ bias,
                        const float* __restrict__ dinv, float* __restrict__ H, int n) {
    const int warp = (blockIdx.x * blockDim.x + threadIdx.x) >> 5;
    const int lane = threadIdx.x & 31;
    const int half = lane >> 4;
    const int sub = lane & 15;
    const int node = warp * 2 + half;
    const unsigned hmask = half ? 0xFFFF0000u : 0x0000FFFFu;
    const bool valid = node < n;

    const int c0 = sub * 4;
    const bool act = valid && (c0 < FOUT);

    float4 acc = make_float4(0.f, 0.f, 0.f, 0.f);
    if (act) {
        float di = dinv[node];
        float ws = di * di;
        float4 v = *reinterpret_cast<const float4*>(xW + (size_t)node * FOUT + c0);
        float4 b = *reinterpret_cast<const float4*>(bias + c0);
        acc.x = fmaf(ws, v.x, b.x);
        acc.y = fmaf(ws, v.y, b.y);
        acc.z = fmaf(ws, v.z, b.z);
        acc.w = fmaf(ws, v.w, b.w);
    }

    int e = valid ? rowptr[node] : 0;
    const int end = valid ? rowptr[node + 1] : 0;

    int2 pr = make_int2(0, 0);
    if (e + sub < end) pr = __ldg(&meta[e + sub]);

    while (e < end) {
        const int cnt = min(end - e, 16);
        const int2 cur = pr;
        const int en = e + 16;
        if (en + sub < end) pr = __ldg(&meta[en + sub]);   // prefetch next chunk

        if (cnt == 16) {
#pragma unroll
            for (int j = 0; j < 16; j++) {
                int s = __shfl_sync(hmask, cur.x, j, 16);
                float w = __int_as_float(__shfl_sync(hmask, cur.y, j, 16));
                if (act) {
                    float4 v = *reinterpret_cast<const float4*>(xW + (size_t)s * FOUT + c0);
                    acc.x = fmaf(w, v.x, acc.x);
                    acc.y = fmaf(w, v.y, acc.y);
                    acc.z = fmaf(w, v.z, acc.z);
                    acc.w = fmaf(w, v.w, acc.w);
                }
            }
        } else {
            for (int j = 0; j < cnt; j++) {
                int s = __shfl_sync(hmask, cur.x, j, 16);
                float w = __int_as_float(__shfl_sync(hmask, cur.y, j, 16));
                if (act) {
                    float4 v = *reinterpret_cast<const float4*>(xW + (size_t)s * FOUT + c0);
                    acc.x = fmaf(w, v.x, acc.x);
                    acc.y = fmaf(w, v.y, acc.y);
                    acc.z = fmaf(w, v.z, acc.z);
                    acc.w = fmaf(w, v.w, acc.w);
                }
            }
        }
        e = en;
    }

    if (act)
        *reinterpret_cast<float4*>(H + (size_t)node * FOUT + c0) = acc;
}

// ---------------- host launcher ----------------

extern "C" void kernel_launch(void* const* d_in, const int* in_sizes, int n_in,
                              void* d_out, int out_size) {
    const float* x  = (const float*)d_in[0];
    const int*   ei = (const int*)d_in[1];
    const float* ew = (const float*)d_in[2];
    const float* W1 = (const float*)d_in[3];
    const float* b1 = (const float*)d_in[4];
    const float* W2 = (const float*)d_in[5];
    const float* b2 = (const float*)d_in[6];
    const float* W3 = (const float*)d_in[7];
    const float* b3 = (const float*)d_in[8];
    float* out = (float*)d_out;

    const int n = in_sizes[0] / 128;
    const int E = in_sizes[2];
    const int* src = ei;
    const int* dst = ei + E;

    float *A, *B, *dinv;
    int *rowptr, *wpos;
    int2 *meta;
    unsigned long long *pack, *state;
    cudaGetSymbolAddress((void**)&A, g_A);
    cudaGetSymbolAddress((void**)&B, g_B);
    cudaGetSymbolAddress((void**)&dinv, g_dinv);
    cudaGetSymbolAddress((void**)&pack, g_pack);
    cudaGetSymbolAddress((void**)&state, g_state);
    cudaGetSymbolAddress((void**)&rowptr, g_rowptr);
    cudaGetSymbolAddress((void**)&wpos, g_wpos);
    cudaGetSymbolAddress((void**)&meta, g_meta);

    const int TB = 256;
    dim3 nblk((n + TB - 1) / TB);
    dim3 eblk((E + TB - 1) / TB);
    dim3 aggblk((n + 15) / 16);   // 2 nodes/warp, 8 warps/block
    dim3 gblk((n + 31) / 32);     // 4 rows/warp, 8 warps/block

    // ---- CSR build (layer-invariant): 4 launches ----
    k_init<<<nblk, TB>>>(pack, state, n);
    k_count<<<eblk, TB>>>(ew, dst, pack, E);
    k_scan<<<SCAN_NB, 256>>>(pack, rowptr, wpos, dinv, state, n, E);
    k_scatter<<<eblk, TB>>>(src, dst, ew, dinv, wpos, meta, E);

    // ---- Layer 1: 128 -> 64 ----
    gemm_xw<128, 64, false><<<gblk, TB>>>(x, W1, A, n);
    agg_csr<64><<<aggblk, TB>>>(A, rowptr, meta, b1, dinv, B, n);

    // ---- Layer 2: 64 -> 64 (ReLU fused into GEMM load) ----
    gemm_xw<64, 64, true><<<gblk, TB>>>(B, W2, A, n);
    agg_csr<64><<<aggblk, TB>>>(A, rowptr, meta, b2, dinv, B, n);

    // ---- Layer 3: 64 -> 40 ----
    gemm_xw<64, 40, true><<<gblk, TB>>>(B, W3, A, n);
    agg_csr<40><<<aggblk, TB>>>(A, rowptr, meta, b3, dinv, out, n);
}

// round 6
// speedup vs baseline: 1.4584x; 1.0271x over previous
#include <cuda_runtime.h>
#include <cstdint>

#define N_NODES 50000
#define N_EDGES 1600000
#define SCAN_NB ((N_NODES + 255) / 256)   // 196

// Scratch (device globals: allocation-free, graph-capturable)
__device__ float g_A[N_NODES * 64];                 // xW scratch
__device__ float g_B[N_NODES * 64];                 // H buffer
__device__ float g_dinv[N_NODES];
__device__ unsigned long long g_pack[N_NODES];      // (cnt<<32) | fixpoint(sum ew)
__device__ unsigned long long g_state[SCAN_NB];     // lookback scan state
__device__ int   g_rowptr[N_NODES + 1];
__device__ int   g_wpos[N_NODES];
__device__ int2  g_meta[N_EDGES];                   // (src, dinv[src]*ew) sorted by dst

// ---------------- prelude ----------------

__global__ void k_init(unsigned long long* pack, unsigned long long* state, int n) {
    int i = blockIdx.x * blockDim.x + threadIdx.x;
    if (i < n) pack[i] = 0ull;
    if (i < SCAN_NB) state[i] = 0ull;
}

// One RED.64 per edge: count in hi word, ew in 2^-20 fixed point in lo word.
__global__ void k_count(const float* __restrict__ ew, const int* __restrict__ dst,
                        unsigned long long* __restrict__ pack, int E) {
    int i = blockIdx.x * blockDim.x + threadIdx.x;
    if (i < E) {
        unsigned q = __float2uint_rn(ew[i] * 1048576.0f);
        atomicAdd(&pack[dst[i]], (1ull << 32) | (unsigned long long)q);
    }
}

// Single-kernel exclusive scan (decoupled lookback) + dinv computation.
__global__ void k_scan(const unsigned long long* __restrict__ pack,
                       int* __restrict__ rowptr, int* __restrict__ wpos,
                       float* __restrict__ dinv, unsigned long long* __restrict__ state,
                       int n, int E) {
    __shared__ int sh[256];
    __shared__ int s_prefix;
    const int b = blockIdx.x;
    const int i = b * 256 + threadIdx.x;

    unsigned long long p = (i < n) ? pack[i] : 0ull;
    int v = (int)(p >> 32);
    if (i < n) {
        float deg = 1.0f + (float)(unsigned)(p & 0xFFFFFFFFull) * (1.0f / 1048576.0f);
        dinv[i] = rsqrtf(deg);
    }

    sh[threadIdx.x] = v;
    __syncthreads();
#pragma unroll
    for (int off = 1; off < 256; off <<= 1) {
        int t = (threadIdx.x >= off) ? sh[threadIdx.x - off] : 0;
        __syncthreads();
        sh[threadIdx.x] += t;
        __syncthreads();
    }
    const int incl = sh[threadIdx.x];
    const int total = sh[255];

    if (threadIdx.x < 32) {
        const int lane = threadIdx.x;
        if (lane == 0) {
            unsigned long long st0 =
                ((unsigned long long)total << 2) | (b == 0 ? 2ull : 1ull);
            atomicExch(&state[b], st0);
        }
        int prefix = 0;
        if (b > 0) {
            int j = b - 1;
            while (true) {
                int idx = j - lane;
                unsigned long long s =
                    (idx >= 0) ? atomicAdd(&state[idx], 0ull) : 2ull;
                unsigned st = (unsigned)(s & 3ull);
                unsigned ready = __ballot_sync(0xffffffffu, st != 0u);
                if (ready != 0xffffffffu) continue;
                unsigned inclmask = __ballot_sync(0xffffffffu, st == 2u);
                if (inclmask) {
                    int l2 = __ffs(inclmask) - 1;
                    int contrib = (lane <= l2) ? (int)(s >> 2) : 0;
#pragma unroll
                    for (int o = 16; o; o >>= 1)
                        contrib += __shfl_down_sync(0xffffffffu, contrib, o);
                    prefix += __shfl_sync(0xffffffffu, contrib, 0);
                    break;
                } else {
                    int contrib = (idx >= 0) ? (int)(s >> 2) : 0;
#pragma unroll
                    for (int o = 16; o; o >>= 1)
                        contrib += __shfl_down_sync(0xffffffffu, contrib, o);
                    prefix += __shfl_sync(0xffffffffu, contrib, 0);
                    j -= 32;
                }
            }
            if (lane == 0)
                atomicExch(&state[b],
                           ((unsigned long long)(prefix + total) << 2) | 2ull);
        }
        if (lane == 0) s_prefix = prefix;
    }
    __syncthreads();

    if (i < n) {
        int r = s_prefix + incl - v;
        rowptr[i] = r;
        wpos[i] = r;
        if (i == n - 1) rowptr[n] = E;
    }
}

// Scatter edges into dst-sorted order. Meta weight = dinv[src]*ew ONLY
// (dinv[dst] factored out into the agg epilogue) -> one random gather, not two.
__global__ void k_scatter(const int* __restrict__ src, const int* __restrict__ dst,
                          const float* __restrict__ ew, const float* __restrict__ dinv,
                          int* __restrict__ wpos, int2* __restrict__ meta, int E) {
    int i = blockIdx.x * blockDim.x + threadIdx.x;
    if (i < E) {
        int s = src[i], d = dst[i];
        int p = atomicAdd(&wpos[d], 1);
        float w = dinv[s] * ew[i];
        meta[p] = make_int2(s, __float_as_int(w));
    }
}

// ---------------- GEMM: xW, 4 rows/warp, packed f32x2 FMA ----------------

template <int FIN, int FOUT, bool RELU_IN>
__global__ void gemm_xw(const float* __restrict__ X, const float* __restrict__ W,
                        float* __restrict__ xW, int n) {
    __shared__ float Ws[FIN * FOUT];
    for (int i = threadIdx.x; i < FIN * FOUT; i += blockDim.x) Ws[i] = W[i];
    __syncthreads();

    const int lane = threadIdx.x & 31;
    const int wq = blockIdx.x * (blockDim.x >> 5) + (threadIdx.x >> 5);
    const int row0 = wq * 4;
    if (row0 >= n) return;

    constexpr int XPL = FIN / 32;
    const int c0 = lane * 2;
    const bool act = (c0 < FOUT);

    float xr[4][XPL];
#pragma unroll
    for (int r = 0; r < 4; r++) {
        int row = row0 + r;
        if (row < n) {
            if (XPL == 4) {
                float4 t = reinterpret_cast<const float4*>(X)[row * (FIN / 4) + lane];
                xr[r][0] = t.x; xr[r][1] = t.y; xr[r][2] = t.z; xr[r][3] = t.w;
            } else {
                float2 t = reinterpret_cast<const float2*>(X)[row * (FIN / 2) + lane];
                xr[r][0] = t.x; xr[r][1] = t.y;
            }
            if (RELU_IN) {
#pragma unroll
                for (int j = 0; j < XPL; j++) xr[r][j] = fmaxf(xr[r][j], 0.0f);
            }
        } else {
#pragma unroll
            for (int j = 0; j < XPL; j++) xr[r][j] = 0.0f;
        }
    }

    unsigned long long acc[4] = {0ull, 0ull, 0ull, 0ull};

#pragma unroll
    for (int k = 0; k < FIN; k++) {
        unsigned long long ww = 0ull;
        if (act)
            ww = *reinterpret_cast<const unsigned long long*>(&Ws[k * FOUT + c0]);
#pragma unroll
        for (int r = 0; r < 4; r++) {
            float xk = __shfl_sync(0xffffffffu, xr[r][k % XPL], k / XPL);
            if (act) {
                unsigned long long xx;
                asm("mov.b64 %0, {%1, %1};" : "=l"(xx) : "f"(xk));
                asm("fma.rn.f32x2 %0, %1, %2, %3;"
                    : "=l"(acc[r]) : "l"(xx), "l"(ww), "l"(acc[r]));
            }
        }
    }

    if (act) {
#pragma unroll
        for (int r = 0; r < 4; r++) {
            int row = row0 + r;
            if (row < n) {
                float2 a;
                asm("mov.b64 {%0, %1}, %2;" : "=f"(a.x), "=f"(a.y) : "l"(acc[r]));
                *reinterpret_cast<float2*>(&xW[(size_t)row * FOUT + c0]) = a;
            }
        }
    }
}

// ---------------- CSR aggregation: half-warp per node, float4, prefetched ----
// acc = dinv_d * xW_d  +  sum_e (dinv_s*ew)_e * xW_src ;  out = dinv_d*acc + b

template <int FOUT>
__global__ void agg_csr(const float* __restrict__ xW, const int* __restrict__ rowptr,
                        const int2* __restrict__ meta, const float* __restrict__ bias,
                        const float* __restrict__ dinv, float* __restrict__ H, int n) {
    const int warp = (blockIdx.x * blockDim.x + threadIdx.x) >> 5;
    const int lane = threadIdx.x & 31;
    const int half = lane >> 4;
    const int sub = lane & 15;
    const int node = warp * 2 + half;
    const unsigned hmask = half ? 0xFFFF0000u : 0x0000FFFFu;
    const bool valid = node < n;

    const int c0 = sub * 4;
    const bool act = valid && (c0 < FOUT);

    float di = valid ? dinv[node] : 0.0f;

    float4 acc = make_float4(0.f, 0.f, 0.f, 0.f);
    if (act) {
        float4 v = *reinterpret_cast<const float4*>(xW + (size_t)node * FOUT + c0);
        acc.x = di * v.x;
        acc.y = di * v.y;
        acc.z = di * v.z;
        acc.w = di * v.w;
    }

    int e = valid ? rowptr[node] : 0;
    const int end = valid ? rowptr[node + 1] : 0;

    int2 pr = make_int2(0, 0);
    if (e + sub < end) pr = __ldg(&meta[e + sub]);

    while (e < end) {
        const int cnt = min(end - e, 16);
        const int2 cur = pr;
        const int en = e + 16;
        if (en + sub < end) pr = __ldg(&meta[en + sub]);   // prefetch next chunk

        if (cnt == 16) {
#pragma unroll
            for (int j = 0; j < 16; j++) {
                int s = __shfl_sync(hmask, cur.x, j, 16);
                float w = __int_as_float(__shfl_sync(hmask, cur.y, j, 16));
                if (act) {
                    float4 v = *reinterpret_cast<const float4*>(xW + (size_t)s * FOUT + c0);
                    acc.x = fmaf(w, v.x, acc.x);
                    acc.y = fmaf(w, v.y, acc.y);
                    acc.z = fmaf(w, v.z, acc.z);
                    acc.w = fmaf(w, v.w, acc.w);
                }
            }
        } else {
            for (int j = 0; j < cnt; j++) {
                int s = __shfl_sync(hmask, cur.x, j, 16);
                float w = __int_as_float(__shfl_sync(hmask, cur.y, j, 16));
                if (act) {
                    float4 v = *reinterpret_cast<const float4*>(xW + (size_t)s * FOUT + c0);
                    acc.x = fmaf(w, v.x, acc.x);
                    acc.y = fmaf(w, v.y, acc.y);
                    acc.z = fmaf(w, v.z, acc.z);
                    acc.w = fmaf(w, v.w, acc.w);
                }
            }
        }
        e = en;
    }

    if (act) {
        float4 b = *reinterpret_cast<const float4*>(bias + c0);
        float4 o;
        o.x = fmaf(di, acc.x, b.x);
        o.y = fmaf(di, acc.y, b.y);
        o.z = fmaf(di, acc.z, b.z);
        o.w = fmaf(di, acc.w, b.w);
        *reinterpret_cast<float4*>(H + (size_t)node * FOUT + c0) = o;
    }
}

// ---------------- host launcher ----------------

extern "C" void kernel_launch(void* const* d_in, const int* in_sizes, int n_in,
                              void* d_out, int out_size) {
    const float* x  = (const float*)d_in[0];
    const int*   ei = (const int*)d_in[1];
    const float* ew = (const float*)d_in[2];
    const float* W1 = (const float*)d_in[3];
    const float* b1 = (const float*)d_in[4];
    const float* W2 = (const float*)d_in[5];
    const float* b2 = (const float*)d_in[6];
    const float* W3 = (const float*)d_in[7];
    const float* b3 = (const float*)d_in[8];
    float* out = (float*)d_out;

    const int n = in_sizes[0] / 128;
    const int E = in_sizes[2];
    const int* src = ei;
    const int* dst = ei + E;

    float *A, *B, *dinv;
    int *rowptr, *wpos;
    int2 *meta;
    unsigned long long *pack, *state;
    cudaGetSymbolAddress((void**)&A, g_A);
    cudaGetSymbolAddress((void**)&B, g_B);
    cudaGetSymbolAddress((void**)&dinv, g_dinv);
    cudaGetSymbolAddress((void**)&pack, g_pack);
    cudaGetSymbolAddress((void**)&state, g_state);
    cudaGetSymbolAddress((void**)&rowptr, g_rowptr);
    cudaGetSymbolAddress((void**)&wpos, g_wpos);
    cudaGetSymbolAddress((void**)&meta, g_meta);

    const int TB = 256;
    dim3 nblk((n + TB - 1) / TB);
    dim3 eblk((E + TB - 1) / TB);
    dim3 aggblk((n + 15) / 16);   // 2 nodes/warp, 8 warps/block
    dim3 gblk((n + 31) / 32);     // 4 rows/warp, 8 warps/block

    // Side stream + events (created once, outside capture on the first
    // correctness call; reused identically on every call -> deterministic).
    static cudaStream_t sSide = nullptr;
    static cudaEvent_t evA = nullptr, evB = nullptr;
    if (sSide == nullptr) {
        cudaStreamCreateWithFlags(&sSide, cudaStreamNonBlocking);
        cudaEventCreateWithFlags(&evA, cudaEventDisableTiming);
        cudaEventCreateWithFlags(&evB, cudaEventDisableTiming);
    }

    // ---- fork: gemm1 (independent of CSR build) runs on side stream ----
    cudaEventRecord(evA, 0);
    cudaStreamWaitEvent(sSide, evA, 0);
    gemm_xw<128, 64, false><<<gblk, TB, 0, sSide>>>(x, W1, A, n);
    cudaEventRecord(evB, sSide);

    // ---- CSR build (layer-invariant) on main stream ----
    k_init<<<nblk, TB>>>(pack, state, n);
    k_count<<<eblk, TB>>>(ew, dst, pack, E);
    k_scan<<<SCAN_NB, 256>>>(pack, rowptr, wpos, dinv, state, n, E);
    k_scatter<<<eblk, TB>>>(src, dst, ew, dinv, wpos, meta, E);

    // ---- join: agg1 needs both gemm1 and scatter ----
    cudaStreamWaitEvent(0, evB, 0);
    agg_csr<64><<<aggblk, TB>>>(A, rowptr, meta, b1, dinv, B, n);

    // ---- Layer 2: 64 -> 64 (ReLU fused into GEMM load) ----
    gemm_xw<64, 64, true><<<gblk, TB>>>(B, W2, A, n);
    agg_csr<64><<<aggblk, TB>>>(A, rowptr, meta, b2, dinv, B, n);

    // ---- Layer 3: 64 -> 40 ----
    gemm_xw<64, 40, true><<<gblk, TB>>>(B, W3, A, n);
    agg_csr<40><<<aggblk, TB>>>(A, rowptr, meta, b3, dinv, out, n);
}